// round 17
// baseline (speedup 1.0000x reference)
#include <cuda_runtime.h>
#include <cuda_bf16.h>
#include <cuda_fp16.h>

// ---------------------------------------------------------------------------
// NT-Xent loss, N=8192, D=512. FP8 (e4m3, scale 16) mma.sync m16n8k32 with
// f16 accumulation, upper-triangular tiles (S = Z Z^T symmetric).
// BARRIER-FREE K-loop: B fragments loaded directly from a K-permuted global
// copy (g_zb) via LDG.128 — no B smem, no cp.async, no per-chunk syncs.
// A stays SMEM-resident (natural layout g_za, SW128 + ldmatrix).
// Permutation (per 128B chunk, dwords): d = ks*8 + b1*4 + q  ->  8q + 2ks + b1
// so each thread's full per-chunk fragment set is 32 contiguous bytes.
// Epilogue: f16x2 fma+ex2 (exponent biased +15, removed in final log;
// diagonal cancelled bitwise-exactly), sums in f32.
// 296 CTAs x 512 threads, 2 CTAs/SM. Final logsumexp fused via ticket.
// ---------------------------------------------------------------------------

#define NN      8192
#define DD      512
#define BHALF   4096
#define NTILES  2080
#define NCTAS   296
#define NTHR    512

#define PSC     0.00390625f               // 1/256
#define INV_TAU 14.285714285714286f
// f16 constants: E = rn16(log2e/0.07/256) = 0x2D27, C = rn16(15-20.60993) = 0xC59C
#define E2U     0x2D272D27u
#define NC2U    0xC59CC59Cu
// final log correction: ln2 * (20.6099291555662 - 5.609375)
#define LOGC    10.3975918f

#define A_BYTES  65536       // 128 rows x 512 B (4 chunks x 16 KB)
#define SMEM_BYTES (A_BYTES + 1024)

__device__ __align__(128) unsigned char g_za[(size_t)NN * DD];  // natural (A path)
__device__ __align__(128) unsigned char g_zb[(size_t)NN * DD];  // K-permuted (B path)
__device__ float g_rowsum[NN];
__device__ float g_pos[NN];
__device__ unsigned g_done;

// ------------------------------- helpers -----------------------------------
__device__ __forceinline__ unsigned smem_u32(const void* p) {
    unsigned a;
    asm("{ .reg .u64 t; cvta.to.shared.u64 t, %1; cvt.u32.u64 %0, t; }"
        : "=r"(a) : "l"(p));
    return a;
}
__device__ __forceinline__ unsigned swz(unsigned off) {
    return off ^ ((off >> 3) & 0x70);
}
__device__ __forceinline__ void ldsm_x4(unsigned* r, unsigned addr) {
    asm volatile("ldmatrix.sync.aligned.m8n8.x4.shared.b16 {%0,%1,%2,%3}, [%4];"
                 : "=r"(r[0]), "=r"(r[1]), "=r"(r[2]), "=r"(r[3]) : "r"(addr));
}
// fp8 mma, f16 accumulator (c0: rows lane>>2, cols 2*(lane&3)+{0,1}; c1: row+8)
__device__ __forceinline__ void mma_fp8h(unsigned* c, const unsigned* a,
                                         unsigned b0, unsigned b1) {
    asm volatile(
        "mma.sync.aligned.m16n8k32.row.col.f16.e4m3.e4m3.f16 "
        "{%0,%1}, {%2,%3,%4,%5}, {%6,%7}, {%0,%1};"
        : "+r"(c[0]), "+r"(c[1])
        : "r"(a[0]), "r"(a[1]), "r"(a[2]), "r"(a[3]), "r"(b0), "r"(b1));
}
__device__ __forceinline__ unsigned hfma2u(unsigned a, unsigned b, unsigned c) {
    unsigned d; asm("fma.rn.f16x2 %0,%1,%2,%3;" : "=r"(d) : "r"(a), "r"(b), "r"(c));
    return d;
}
__device__ __forceinline__ unsigned h2ex2(unsigned a) {
    unsigned d; asm("ex2.approx.f16x2 %0,%1;" : "=r"(d) : "r"(a));
    return d;
}
__device__ __forceinline__ float2 h2f2(unsigned a) {
    __half2 h = *(__half2*)&a;
    return __half22float2(h);
}
__device__ __forceinline__ unsigned short cvt2_e4m3(float lo, float hi) {
    unsigned short r;
    asm("cvt.rn.satfinite.e4m3x2.f32 %0, %1, %2;" : "=h"(r) : "f"(hi), "f"(lo));
    return r;
}

// decode flattened tile index -> (I, J)
__device__ __forceinline__ void tile_decode(int t, int& I, int& J) {
    int p = t / 65;
    int l = t - p * 65;
    int n1 = 64 - p;
    if (l < n1) { I = p;      J = p + l; }
    else        { I = 63 - p; J = I + (l - n1); }
}

// ------------------------- kernel 1: normalize -> fp8 x2 -------------------
__global__ __launch_bounds__(256) void ntx_normalize(const float* __restrict__ anchor,
                                                     const float* __restrict__ positive) {
    int gt = blockIdx.x * 256 + threadIdx.x;
    if (gt < NN) g_rowsum[gt] = 0.f;          // graph-replay safe re-init
    if (gt == 0) g_done = 0u;

    int row  = blockIdx.x * 8 + (threadIdx.x >> 5);
    int lane = threadIdx.x & 31;
    const float* src = (row < BHALF) ? (anchor + (size_t)row * DD)
                                     : (positive + (size_t)(row - BHALF) * DD);
    const float4* s4 = (const float4*)src;
    float4 v[4];
    float ss = 0.f;
#pragma unroll
    for (int q = 0; q < 4; q++) {
        v[q] = s4[lane + 32 * q];
        ss += v[q].x * v[q].x + v[q].y * v[q].y + v[q].z * v[q].z + v[q].w * v[q].w;
    }
#pragma unroll
    for (int o = 16; o > 0; o >>= 1) ss += __shfl_xor_sync(0xFFFFFFFFu, ss, o);
    float s16 = 16.0f / fmaxf(sqrtf(ss), 1e-8f);

    // per-lane permuted dword index within a 32-dword chunk:
    // dc = lane -> dnew = ((lane&3)<<3) + ((lane>>3)<<1) + ((lane>>2)&1)
    int perm = ((lane & 3) << 3) + ((lane >> 3) << 1) + ((lane >> 2) & 1);

    unsigned* za = (unsigned*)(g_za + (size_t)row * DD);
    unsigned* zb = (unsigned*)(g_zb + (size_t)row * DD);
#pragma unroll
    for (int q = 0; q < 4; q++) {
        unsigned lo = cvt2_e4m3(v[q].x * s16, v[q].y * s16);
        unsigned hi = cvt2_e4m3(v[q].z * s16, v[q].w * s16);
        unsigned w  = lo | (hi << 16);
        za[lane + 32 * q] = w;                 // natural (A path)
        zb[q * 32 + perm] = w;                 // K-permuted (B path)
    }
}

// ------------------------- kernel 2: upper-tri GEMM + exp-reduce -----------
__global__ __launch_bounds__(NTHR, 2) void ntx_main(float* __restrict__ out) {
    extern __shared__ char smem_raw[];
    unsigned raw  = smem_u32(smem_raw);
    unsigned base = (raw + 1023u) & ~1023u;
    char* sp      = smem_raw + (base - raw);
    unsigned A  = base;

    int tid  = threadIdx.x;
    int wid  = tid >> 5, lane = tid & 31;
    int warpM = wid & 3, warpN = wid >> 2;     // 4 x 4 warp grid, tile 32x32
    int qrow = lane >> 2;

    int c  = blockIdx.x;
    int t0 = (c * NTILES) / NCTAS;
    int t1 = ((c + 1) * NTILES) / NCTAS;

    // compact ldmatrix addressing (A only)
    int sel = lane >> 3, lr = lane & 7;
    unsigned cbx[4];
#pragma unroll
    for (int ks = 0; ks < 4; ks++)
        cbx[ks] = ((unsigned)(ks * 32 + ((sel >> 1) << 4))) ^ ((unsigned)lr << 4);
    unsigned arowb[2];
#pragma unroll
    for (int mf = 0; mf < 2; mf++)
        arowb[mf] = (unsigned)((warpM * 32 + mf * 16 + ((sel & 1) << 3) + lr) * 128);

    // per-lane B base offset (within a column block): row warpN*32 + lane>>2,
    // byte (lane&3)*32 inside each 128B chunk
    size_t bline = ((size_t)((warpN << 5) + (lane >> 2)) << 9) + (size_t)((lane & 3) << 5);

    unsigned acc[2][4][2];                     // f16x2 accumulators (32x32 tile)
    float rsum[2][2] = {{0.f, 0.f}, {0.f, 0.f}};
    int curI = -1;

    for (int t = t0; t < t1; t++) {
        int I, J;
        tile_decode(t, I, J);
        int rowbase = I << 7, colbase = J << 7;

        if (I != curI) {
            if (curI >= 0) {
#pragma unroll
                for (int mf = 0; mf < 2; mf++)
#pragma unroll
                    for (int h = 0; h < 2; h++) {
                        float v = rsum[mf][h];
                        v += __shfl_xor_sync(0xFFFFFFFFu, v, 1);
                        v += __shfl_xor_sync(0xFFFFFFFFu, v, 2);
                        if ((lane & 3) == 0)
                            atomicAdd(&g_rowsum[(curI << 7) + warpM * 32 + mf * 16 + h * 8 + qrow], v);
                        rsum[mf][h] = 0.f;
                    }
            }
            __syncthreads();                   // all readers of old A done
#pragma unroll
            for (int it = 0; it < 8; it++) {
                int x = tid + it * NTHR;
                int r = x >> 5, u = x & 31, ck = u >> 3, c8 = u & 7;
                const uint4* src = (const uint4*)(g_za + ((size_t)(rowbase + r) << 9)
                                                  + ck * 128 + c8 * 16);
                *(uint4*)(sp + ck * 16384 + swz((unsigned)(r * 128 + c8 * 16))) = *src;
            }
            __syncthreads();
            curI = I;
        }

#pragma unroll
        for (int mf = 0; mf < 2; mf++)
#pragma unroll
            for (int nf = 0; nf < 4; nf++) {
                acc[mf][nf][0] = 0u;
                acc[mf][nf][1] = 0u;
            }

        const char* bptr = (const char*)g_zb + (((size_t)colbase) << 9) + bline;

        // ---- barrier-free K loop: 4 chunks x (2 halves x 2 ks) ----
#pragma unroll
        for (int k = 0; k < 4; k++) {
            unsigned Ac = A + k * 16384;
            const char* bk = bptr + k * 128;
#pragma unroll
            for (int half = 0; half < 2; half++) {
                uint4 bf[4];
#pragma unroll
                for (int nb = 0; nb < 4; nb++)
                    bf[nb] = *(const uint4*)(bk + nb * 4096 + half * 16);
#pragma unroll
                for (int ks2 = 0; ks2 < 2; ks2++) {
                    int ks = half * 2 + ks2;
                    unsigned afr[2][4];
                    ldsm_x4(afr[0], Ac + arowb[0] + cbx[ks]);
                    ldsm_x4(afr[1], Ac + arowb[1] + cbx[ks]);
#pragma unroll
                    for (int mf = 0; mf < 2; mf++)
#pragma unroll
                        for (int nb = 0; nb < 4; nb++)
                            mma_fp8h(acc[mf][nb], afr[mf],
                                     ks2 ? bf[nb].z : bf[nb].x,
                                     ks2 ? bf[nb].w : bf[nb].y);
                }
            }
        }

        // ---- epilogue: f16x2 fma+ex2 (bias +15), f32 sums ----
        bool isdiag = (J == I);
        bool ispos  = (J == I + 32);

        if (isdiag | ispos) {
#pragma unroll
            for (int mf = 0; mf < 2; mf++)
#pragma unroll
                for (int h = 0; h < 2; h++) {
                    int rloc = warpM * 32 + mf * 16 + h * 8 + qrow;
                    int cc = rloc - warpN * 32;
                    if (cc >= 0 && cc < 32 && (((cc >> 1) & 3) == (lane & 3))) {
                        unsigned hp = acc[mf][cc >> 3][h];
                        if (isdiag) {
                            // identical f16 recompute -> bitwise-exact cancel
                            float2 fe = h2f2(h2ex2(hfma2u(hp, E2U, NC2U)));
                            rsum[mf][h] -= (cc & 1) ? fe.y : fe.x;
                        }
                        if (ispos) {
                            __half2 hv = *(__half2*)&hp;
                            float v = (cc & 1) ? __high2float(hv) : __low2float(hv);
                            g_pos[rowbase + rloc] = v * PSC;
                            g_pos[rowbase + rloc + BHALF] = v * PSC;
                        }
                    }
                }
        }

        float colp[8];
#pragma unroll
        for (int q = 0; q < 8; q++) colp[q] = 0.f;
#pragma unroll
        for (int mf = 0; mf < 2; mf++) {
            float slo = 0.f, shi = 0.f;
#pragma unroll
            for (int nf = 0; nf < 4; nf++) {
                unsigned eh0 = h2ex2(hfma2u(acc[mf][nf][0], E2U, NC2U));
                unsigned eh1 = h2ex2(hfma2u(acc[mf][nf][1], E2U, NC2U));
                float2 f01 = h2f2(eh0);
                float2 f23 = h2f2(eh1);
                slo += f01.x + f01.y;
                shi += f23.x + f23.y;
                colp[nf * 2]     += f01.x + f23.x;
                colp[nf * 2 + 1] += f01.y + f23.y;
            }
            rsum[mf][0] += slo;
            rsum[mf][1] += shi;
        }

        if (!isdiag) {
#pragma unroll
            for (int q = 0; q < 8; q++) {
                float v = colp[q];
                v += __shfl_xor_sync(0xFFFFFFFFu, v, 4);
                v += __shfl_xor_sync(0xFFFFFFFFu, v, 8);
                v += __shfl_xor_sync(0xFFFFFFFFu, v, 16);
                if (lane < 4) {
                    int ccol = (q >> 1) * 8 + 2 * lane + (q & 1);
                    atomicAdd(&g_rowsum[colbase + warpN * 32 + ccol], v);
                }
            }
        }
    }

    // final row flush
#pragma unroll
    for (int mf = 0; mf < 2; mf++)
#pragma unroll
        for (int h = 0; h < 2; h++) {
            float v = rsum[mf][h];
            v += __shfl_xor_sync(0xFFFFFFFFu, v, 1);
            v += __shfl_xor_sync(0xFFFFFFFFu, v, 2);
            if ((lane & 3) == 0 && curI >= 0)
                atomicAdd(&g_rowsum[(curI << 7) + warpM * 32 + mf * 16 + h * 8 + qrow], v);
        }

    // ---- completion ticket: last CTA computes the loss ----
    __threadfence();
    __syncthreads();
    __shared__ unsigned ticket;
    if (tid == 0) ticket = atomicAdd(&g_done, 1u);
    __syncthreads();
    if (ticket == NCTAS - 1) {
        float local_s = 0.f;
        for (int r = tid; r < NN; r += NTHR)
            local_s += (1.0f - g_pos[r]) * INV_TAU + __logf(g_rowsum[r]) - LOGC;
#pragma unroll
        for (int o = 16; o > 0; o >>= 1) local_s += __shfl_xor_sync(0xFFFFFFFFu, local_s, o);
        __shared__ float red[16];
        if (lane == 0) red[wid] = local_s;
        __syncthreads();
        if (tid < 16) {
            float v = red[tid];
#pragma unroll
            for (int o = 8; o > 0; o >>= 1) v += __shfl_xor_sync(0xFFFFu, v, o);
            if (tid == 0) out[0] = v * (1.0f / (float)NN);
        }
    }
}

// ---------------------------------------------------------------------------
extern "C" void kernel_launch(void* const* d_in, const int* in_sizes, int n_in,
                              void* d_out, int out_size) {
    (void)in_sizes; (void)n_in; (void)out_size;
    const float* anchor   = (const float*)d_in[0];
    const float* positive = (const float*)d_in[1];

    cudaFuncSetAttribute(ntx_main, cudaFuncAttributeMaxDynamicSharedMemorySize,
                         SMEM_BYTES);

    ntx_normalize<<<NN / 8, 256>>>(anchor, positive);
    ntx_main<<<NCTAS, NTHR, SMEM_BYTES>>>((float*)d_out);
}